// round 3
// baseline (speedup 1.0000x reference)
#include <cuda_runtime.h>

// GaussianKernelBiasingDensity: out_b = -f(z_b)^T (W+eps) g(t_b)
// f_i(z) = exp(-50 (z - zmean_i)^2), g_j(t) = exp(-50 (t - tmean_j)^2)
// Separable factorization of the 16384-component Gaussian mixture:
// 256 exps + 16384 FMAs per batch element instead of 16384 exps.

#define T_BINS 128
#define Z_BINS 128
#define NTHREADS 256
#define BATCH_PER_BLOCK 32
#define JS 16   // j-slice width per warp (8 warps * 16 = 128)

// smem: W(16384) + ABz(256 as float2) + ABt(256) + red(256) floats
#define SMEM_FLOATS (16384 + 256 + 256 + 256)
#define SMEM_BYTES (SMEM_FLOATS * 4)

__device__ __forceinline__ float ex2f(float x) {
    float r;
    asm("ex2.approx.ftz.f32 %0, %1;" : "=f"(r) : "f"(x));
    return r;
}

__global__ __launch_bounds__(NTHREADS)
void gkb_kernel(const float* __restrict__ Zv,
                const float* __restrict__ Tv,
                const float* __restrict__ means,
                const float* __restrict__ weights,
                float* __restrict__ out, int n)
{
    extern __shared__ float smem[];
    float*  Wsh = smem;                       // 16384 floats (W + eps)
    float2* ABz = (float2*)(smem + 16384);    // 128 x {A, B} for z-dim
    float2* ABt = (float2*)(smem + 16384 + 256);
    float*  red = smem + 16384 + 512;         // 256 floats

    const float L2E = 1.4426950408889634f;
    const float EPS = 0.01f;

    int tid = threadIdx.x;

    // ---- stage W' = weights + eps into smem (vectorized) ----
    const float4* w4  = (const float4*)weights;
    float4*       ws4 = (float4*)Wsh;
    #pragma unroll 4
    for (int k = tid; k < (Z_BINS * T_BINS) / 4; k += NTHREADS) {
        float4 v = w4[k];
        v.x += EPS; v.y += EPS; v.z += EPS; v.w += EPS;
        ws4[k] = v;
    }
    // ---- per-bin exp constants: arg = z*A + (B + base), all pre-scaled by log2(e) ----
    if (tid < Z_BINS) {
        float zm = means[tid * (T_BINS * 2)];     // means[i][0][0]
        ABz[tid] = make_float2(100.f * L2E * zm, -50.f * L2E * zm * zm);
        float tm = means[tid * 2 + 1];            // means[0][j][1]
        ABt[tid] = make_float2(100.f * L2E * tm, -50.f * L2E * tm * tm);
    }
    __syncthreads();

    int lane = tid & 31;
    int w    = tid >> 5;                 // warp id 0..7 -> j-slice
    int b    = blockIdx.x * BATCH_PER_BLOCK + lane;
    bool valid = (b < n);

    float z = valid ? Zv[b] : 0.f;
    float t = valid ? Tv[b] : 0.f;
    float basez = -50.f * L2E * z * z;
    float baset = -50.f * L2E * t * t;

    // ---- g_j for this warp's 16 j's ----
    float g[JS];
    #pragma unroll
    for (int jj = 0; jj < JS; jj++) {
        float2 ab = ABt[w * JS + jj];
        g[jj] = ex2f(fmaf(t, ab.x, baset + ab.y));
    }

    // ---- h[jj] = sum_i f_i * W'[i][jj]  (16 independent FFMA chains) ----
    float h[JS];
    #pragma unroll
    for (int q = 0; q < JS; q++) h[q] = 0.f;

    const int joff = w * JS;
    #pragma unroll 4
    for (int i = 0; i < Z_BINS; i++) {
        float2 ab = ABz[i];                            // LDS.64 broadcast
        float fi  = ex2f(fmaf(z, ab.x, basez + ab.y)); // MUFU.EX2
        const float4* wr = (const float4*)(Wsh + i * T_BINS + joff); // broadcast
        #pragma unroll
        for (int q = 0; q < 4; q++) {
            float4 v = wr[q];
            h[4*q+0] = fmaf(fi, v.x, h[4*q+0]);
            h[4*q+1] = fmaf(fi, v.y, h[4*q+1]);
            h[4*q+2] = fmaf(fi, v.z, h[4*q+2]);
            h[4*q+3] = fmaf(fi, v.w, h[4*q+3]);
        }
    }

    // ---- partial = sum_j g_j * h_j ----
    float partial = 0.f;
    #pragma unroll
    for (int q = 0; q < JS; q++) partial = fmaf(g[q], h[q], partial);

    // ---- reduce the 8 warp-partials per batch element ----
    red[w * 32 + lane] = partial;
    __syncthreads();
    if (w == 0 && valid) {
        float s = 0.f;
        #pragma unroll
        for (int k = 0; k < 8; k++) s += red[k * 32 + lane];
        out[b] = -s;
    }
}

extern "C" void kernel_launch(void* const* d_in, const int* in_sizes, int n_in,
                              void* d_out, int out_size) {
    const float* z       = (const float*)d_in[0];
    const float* t       = (const float*)d_in[1];
    const float* means   = (const float*)d_in[2];
    const float* weights = (const float*)d_in[3];
    float* out = (float*)d_out;
    int n = in_sizes[0];

    cudaFuncSetAttribute(gkb_kernel,
                         cudaFuncAttributeMaxDynamicSharedMemorySize, SMEM_BYTES);

    int grid = (n + BATCH_PER_BLOCK - 1) / BATCH_PER_BLOCK;  // 512 for B=16384
    gkb_kernel<<<grid, NTHREADS, SMEM_BYTES>>>(z, t, means, weights, out, n);
}

// round 7
// speedup vs baseline: 1.3924x; 1.3924x over previous
#include <cuda_runtime.h>

// GaussianKernelBiasingDensity: out_b = -f(z_b)^T (W+eps) g(t_b)
// Separable: f_i(z)=exp(-50(z-zm_i)^2), g_j(t)=exp(-50(t-tm_j)^2).
// R3: packed fp32x2 FFMA (j-pairs in lanes), 2 batch elements/thread,
//     g computed post-loop, reg cap 128 for pipelining.

#define T_BINS 128
#define Z_BINS 128
#define NTHREADS 256
#define BPB 64          // batch elements per block (2 per thread-lane)
#define JS 16           // j-slice per warp (8 warps * 16 = 128)

// smem: W(16384) + ABz(128 f2) + ABt(128 f2) + red(256 f2)
#define SMEM_FLOATS (16384 + 256 + 256 + 512)
#define SMEM_BYTES  (SMEM_FLOATS * 4)

typedef unsigned long long u64;

__device__ __forceinline__ float ex2f(float x) {
    float r; asm("ex2.approx.ftz.f32 %0, %1;" : "=f"(r) : "f"(x)); return r;
}
__device__ __forceinline__ u64 fma2(u64 a, u64 b, u64 c) {
    u64 d; asm("fma.rn.f32x2 %0, %1, %2, %3;" : "=l"(d) : "l"(a), "l"(b), "l"(c));
    return d;
}
__device__ __forceinline__ u64 dup2(float x) {
    u64 d; asm("mov.b64 %0, {%1, %1};" : "=l"(d) : "f"(x)); return d;
}
__device__ __forceinline__ u64 pack2(float lo, float hi) {
    u64 d; asm("mov.b64 %0, {%1, %2};" : "=l"(d) : "f"(lo), "f"(hi)); return d;
}
__device__ __forceinline__ float2 unpack2(u64 v) {
    float2 r; asm("mov.b64 {%0, %1}, %2;" : "=f"(r.x), "=f"(r.y) : "l"(v)); return r;
}

__global__ __launch_bounds__(NTHREADS, 2)
void gkb_kernel(const float* __restrict__ Zv,
                const float* __restrict__ Tv,
                const float* __restrict__ means,
                const float* __restrict__ weights,
                float* __restrict__ out, int n)
{
    extern __shared__ float smem[];
    float*  Wsh = smem;                          // 16384 floats (W + eps)
    float2* ABz = (float2*)(smem + 16384);       // 128 x {A, B}
    float2* ABt = (float2*)(smem + 16384 + 256);
    float2* red = (float2*)(smem + 16384 + 512); // 256 float2

    const float L2E = 1.4426950408889634f;
    const float EPS = 0.01f;
    int tid = threadIdx.x;

    // ---- stage W' = weights + eps ----
    const float4* w4  = (const float4*)weights;
    float4*       ws4 = (float4*)Wsh;
    #pragma unroll 4
    for (int k = tid; k < (Z_BINS * T_BINS) / 4; k += NTHREADS) {
        float4 v = w4[k];
        v.x += EPS; v.y += EPS; v.z += EPS; v.w += EPS;
        ws4[k] = v;
    }
    // ---- per-bin exp constants (log2e folded): arg = z*A + (B + base) ----
    if (tid < Z_BINS) {
        float zm = means[tid * (T_BINS * 2)];     // means[i][0][0]
        ABz[tid] = make_float2(100.f * L2E * zm, -50.f * L2E * zm * zm);
        float tm = means[tid * 2 + 1];            // means[0][j][1]
        ABt[tid] = make_float2(100.f * L2E * tm, -50.f * L2E * tm * tm);
    }
    __syncthreads();

    int lane = tid & 31;
    int w    = tid >> 5;
    int ba   = blockIdx.x * BPB + lane;     // batch element A
    int bb   = ba + 32;                     // batch element B
    bool va = (ba < n), vb = (bb < n);

    float za = va ? Zv[ba] : 0.f,  ta = va ? Tv[ba] : 0.f;
    float zb = vb ? Zv[bb] : 0.f,  tb = vb ? Tv[bb] : 0.f;
    float baseza = -50.f * L2E * za * za;
    float basezb = -50.f * L2E * zb * zb;
    float baseta = -50.f * L2E * ta * ta;
    float basetb = -50.f * L2E * tb * tb;

    // ---- main loop: h2[q] accumulates j-pairs (joff+2q, joff+2q+1) ----
    u64 ha[JS/2], hb[JS/2];
    #pragma unroll
    for (int q = 0; q < JS/2; q++) { ha[q] = 0ull; hb[q] = 0ull; }

    const int joff = w * JS;
    #pragma unroll 4
    for (int i = 0; i < Z_BINS; i++) {
        float2 ab = ABz[i];                               // LDS.64 broadcast
        float fa = ex2f(fmaf(za, ab.x, ab.y + baseza));
        float fb = ex2f(fmaf(zb, ab.x, ab.y + basezb));
        u64 fa2 = dup2(fa), fb2 = dup2(fb);
        const ulonglong2* wr = (const ulonglong2*)(Wsh + i * T_BINS + joff);
        #pragma unroll
        for (int q = 0; q < 4; q++) {
            ulonglong2 wv = wr[q];                        // LDS.128 broadcast: 2 j-pairs
            ha[2*q+0] = fma2(fa2, wv.x, ha[2*q+0]);
            ha[2*q+1] = fma2(fa2, wv.y, ha[2*q+1]);
            hb[2*q+0] = fma2(fb2, wv.x, hb[2*q+0]);
            hb[2*q+1] = fma2(fb2, wv.y, hb[2*q+1]);
        }
    }

    // ---- epilogue: packed dot with g ----
    u64 acca = 0ull, accb = 0ull;
    #pragma unroll
    for (int q = 0; q < JS/2; q++) {
        float2 ab0 = ABt[joff + 2*q + 0];
        float2 ab1 = ABt[joff + 2*q + 1];
        float ga0 = ex2f(fmaf(ta, ab0.x, ab0.y + baseta));
        float ga1 = ex2f(fmaf(ta, ab1.x, ab1.y + baseta));
        float gb0 = ex2f(fmaf(tb, ab0.x, ab0.y + basetb));
        float gb1 = ex2f(fmaf(tb, ab1.x, ab1.y + basetb));
        acca = fma2(pack2(ga0, ga1), ha[q], acca);
        accb = fma2(pack2(gb0, gb1), hb[q], accb);
    }
    float2 pa = unpack2(acca), pb = unpack2(accb);
    red[w * 32 + lane] = make_float2(pa.x + pa.y, pb.x + pb.y);
    __syncthreads();

    // ---- reduce 8 warp-partials per batch element ----
    if (w == 0) {
        float sa = 0.f, sb = 0.f;
        #pragma unroll
        for (int k = 0; k < 8; k++) {
            float2 v = red[k * 32 + lane];
            sa += v.x; sb += v.y;
        }
        if (va) out[ba] = -sa;
        if (vb) out[bb] = -sb;
    }
}

extern "C" void kernel_launch(void* const* d_in, const int* in_sizes, int n_in,
                              void* d_out, int out_size) {
    const float* z       = (const float*)d_in[0];
    const float* t       = (const float*)d_in[1];
    const float* means   = (const float*)d_in[2];
    const float* weights = (const float*)d_in[3];
    float* out = (float*)d_out;
    int n = in_sizes[0];

    cudaFuncSetAttribute(gkb_kernel,
                         cudaFuncAttributeMaxDynamicSharedMemorySize, SMEM_BYTES);

    int grid = (n + BPB - 1) / BPB;   // 256 for B=16384
    gkb_kernel<<<grid, NTHREADS, SMEM_BYTES>>>(z, t, means, weights, out, n);
}